// round 13
// baseline (speedup 1.0000x reference)
#include <cuda_runtime.h>
#include <cuda_bf16.h>
#include <math.h>
#include <stdint.h>

#define NN 169343
#define EE_MAX 2400000
#define D_IN 128
#define D_H  256
#define D_OUT 40
#define EPS 1e-5f
#define NB_SCAN ((NN + 255) / 256)   // 662

// ---------------- scratch (allocation-free __device__ globals) -------------------
__device__ float g_dinv[NN];
__device__ float g_selfnorm[NN];
__device__ int   g_counts[NN];
__device__ int   g_cursor[NN];
__device__ int   g_rowptr[NN + 1];
__device__ int   g_partial[NB_SCAN];
__device__ int2  g_csr[EE_MAX];            // {src, w-as-bits} interleaved
__device__ float g_s1[D_H], g_o1[D_H];     // fused BN1 params
__device__ float g_s2[D_H], g_o2[D_H];     // fused BN2 params
__device__ float g_b0[(size_t)NN * D_H];   // H (gemm output)
__device__ float g_b1[(size_t)NN * D_H];   // act1
__device__ float g_b2[(size_t)NN * D_H];   // agg(x) / emb fallback

template <int SEL>
__device__ __forceinline__ float* selbuf(float* ext) {
    if constexpr (SEL == 0) return g_b0;
    else if constexpr (SEL == 1) return g_b1;
    else if constexpr (SEL == 2) return g_b2;
    else return ext;
}
template <int SEL>
__device__ __forceinline__ const float* selbuf_c(const float* ext) {
    if constexpr (SEL == 0) return g_b0;
    else if constexpr (SEL == 1) return g_b1;
    else if constexpr (SEL == 2) return g_b2;
    else return ext;
}

// ---------------- CSR build ------------------------------------------------------
__global__ void k_zero_counts() {
    int i = blockIdx.x * blockDim.x + threadIdx.x;
    if (i < NN) g_counts[i] = 0;
}
__global__ void k_count(const int* __restrict__ ei, int E) {
    int e = blockIdx.x * blockDim.x + threadIdx.x;
    if (e < E) atomicAdd(&g_counts[ei[E + e]], 1);
}
__global__ void k_scan1() {
    __shared__ int s[256];
    int gid = blockIdx.x * 256 + threadIdx.x;
    int v = (gid < NN) ? g_counts[gid] : 0;
    s[threadIdx.x] = v;
    __syncthreads();
#pragma unroll
    for (int off = 1; off < 256; off <<= 1) {
        int t = (threadIdx.x >= off) ? s[threadIdx.x - off] : 0;
        __syncthreads();
        s[threadIdx.x] += t;
        __syncthreads();
    }
    if (gid < NN) g_rowptr[gid] = s[threadIdx.x] - v;   // exclusive
    if (threadIdx.x == 255) g_partial[blockIdx.x] = s[255];
}
__global__ void k_scan2() {
    __shared__ int s[1024];
    int v = (threadIdx.x < NB_SCAN) ? g_partial[threadIdx.x] : 0;
    s[threadIdx.x] = v;
    __syncthreads();
#pragma unroll
    for (int off = 1; off < 1024; off <<= 1) {
        int t = (threadIdx.x >= off) ? s[threadIdx.x - off] : 0;
        __syncthreads();
        s[threadIdx.x] += t;
        __syncthreads();
    }
    if (threadIdx.x < NB_SCAN) g_partial[threadIdx.x] = s[threadIdx.x] - v;
}
__global__ void k_scan3(int E) {
    int gid = blockIdx.x * 256 + threadIdx.x;
    if (gid < NN) g_rowptr[gid] += g_partial[blockIdx.x];
    if (gid == 0) g_rowptr[NN] = E;
}
__global__ void k_norms() {
    int i = blockIdx.x * blockDim.x + threadIdx.x;
    if (i < NN) {
        int r0 = g_rowptr[i];
        float d = (float)(g_rowptr[i + 1] - r0 + 1);
        g_dinv[i]     = rsqrtf(d);
        g_selfnorm[i] = 1.0f / d;
        g_cursor[i]   = r0;
    }
}
__global__ void k_fill(const int* __restrict__ ei, int E) {
    int e = blockIdx.x * blockDim.x + threadIdx.x;
    if (e < E) {
        int src = ei[e];
        int dst = ei[E + e];
        int pos = atomicAdd(&g_cursor[dst], 1);
        float w = g_dinv[src] * g_dinv[dst];
        g_csr[pos] = make_int2(src, __float_as_int(w));
    }
}
__global__ void k_bnparams(const float* __restrict__ b1, const float* __restrict__ g1,
                           const float* __restrict__ be1, const float* __restrict__ m1,
                           const float* __restrict__ v1,
                           const float* __restrict__ b2, const float* __restrict__ g2,
                           const float* __restrict__ be2, const float* __restrict__ m2,
                           const float* __restrict__ v2) {
    int c = threadIdx.x;
    if (c < D_H) {
        float s = g1[c] * rsqrtf(v1[c] + EPS);
        g_s1[c] = s;
        g_o1[c] = be1[c] + (b1[c] - m1[c]) * s;
        s = g2[c] * rsqrtf(v2[c] + EPS);
        g_s2[c] = s;
        g_o2[c] = be2[c] + (b2[c] - m2[c]) * s;
    }
}

// ---------------- CSR aggregation ------------------------------------------------
template <int C4, int TPR, int ROWST4, int SRCSEL, int DSTSEL, int EPI>
__global__ void k_csr_agg(const float* __restrict__ srcExt, float* dstExt, int colOff4) {
    const float* __restrict__ SRC = selbuf_c<SRCSEL>(srcExt);
    float* DST = selbuf<DSTSEL>(dstExt);
    constexpr int RPB = 256 / TPR;
    int row = blockIdx.x * RPB + threadIdx.x / TPR;
    int c   = threadIdx.x % TPR;
    if (row >= NN || c >= C4) return;
    int col4 = colOff4 + c;

    float sn = g_selfnorm[row];
    float4 h = *((const float4*)(SRC + (size_t)row * (ROWST4 * 4)) + col4);
    float4 acc = make_float4(h.x * sn, h.y * sn, h.z * sn, h.w * sn);

    int e0 = g_rowptr[row], e1 = g_rowptr[row + 1];
#pragma unroll 2
    for (int e = e0; e < e1; e++) {
        int2 p = g_csr[e];
        float w = __int_as_float(p.y);
        float4 v = *((const float4*)(SRC + (size_t)p.x * (ROWST4 * 4)) + col4);
        acc.x = fmaf(v.x, w, acc.x);
        acc.y = fmaf(v.y, w, acc.y);
        acc.z = fmaf(v.z, w, acc.z);
        acc.w = fmaf(v.w, w, acc.w);
    }
    if constexpr (EPI == 1) {
        float4 s4 = *((const float4*)g_s2 + col4);
        float4 o4 = *((const float4*)g_o2 + col4);
        acc.x = fmaxf(fmaf(acc.x, s4.x, o4.x), 0.0f);
        acc.y = fmaxf(fmaf(acc.y, s4.y, o4.y), 0.0f);
        acc.z = fmaxf(fmaf(acc.z, s4.z, o4.z), 0.0f);
        acc.w = fmaxf(fmaf(acc.w, s4.w, o4.w), 0.0f);
    }
    *((float4*)(DST + (size_t)row * (ROWST4 * 4)) + col4) = acc;
}

// ---------------- fused layer-3 agg + bias + log-softmax -------------------------
// SRC rows of 40 floats (logits pre-agg in g_b0). 16 lanes per row, lanes 0..9
// active (10 float4 per row). Width-16 shuffles for max/sum.
template <int SRCSEL>
__global__ void k_agg_softmax(const float* __restrict__ srcExt,
                              const float* __restrict__ b3, float* __restrict__ OUT) {
    const float* __restrict__ SRC = selbuf_c<SRCSEL>(srcExt);
    int tid = threadIdx.x;
    int row = blockIdx.x * 16 + tid / 16;
    int c   = tid % 16;
    int rowc = (row < NN) ? row : NN - 1;
    bool active = (c < 10);

    float4 acc = make_float4(0.f, 0.f, 0.f, 0.f);
    if (active) {
        float sn = g_selfnorm[rowc];
        float4 h = *((const float4*)(SRC + (size_t)rowc * D_OUT) + c);
        acc = make_float4(h.x * sn, h.y * sn, h.z * sn, h.w * sn);
        int e0 = g_rowptr[rowc], e1 = g_rowptr[rowc + 1];
#pragma unroll 2
        for (int e = e0; e < e1; e++) {
            int2 p = g_csr[e];
            float w = __int_as_float(p.y);
            float4 v = *((const float4*)(SRC + (size_t)p.x * D_OUT) + c);
            acc.x = fmaf(v.x, w, acc.x);
            acc.y = fmaf(v.y, w, acc.y);
            acc.z = fmaf(v.z, w, acc.z);
            acc.w = fmaf(v.w, w, acc.w);
        }
        float4 bb = *((const float4*)b3 + c);
        acc.x += bb.x; acc.y += bb.y; acc.z += bb.z; acc.w += bb.w;
    }
    float m = active ? fmaxf(fmaxf(acc.x, acc.y), fmaxf(acc.z, acc.w)) : -1e30f;
#pragma unroll
    for (int o = 8; o > 0; o >>= 1)
        m = fmaxf(m, __shfl_xor_sync(0xffffffffu, m, o, 16));
    float s = active ? (__expf(acc.x - m) + __expf(acc.y - m) +
                        __expf(acc.z - m) + __expf(acc.w - m)) : 0.0f;
#pragma unroll
    for (int o = 8; o > 0; o >>= 1)
        s += __shfl_xor_sync(0xffffffffu, s, o, 16);
    float ls = __logf(s);
    if (active && row < NN) {
        float4 o4 = make_float4(acc.x - m - ls, acc.y - m - ls,
                                acc.z - m - ls, acc.w - m - ls);
        *((float4*)(OUT + (size_t)row * D_OUT) + c) = o4;
    }
}

// ---------------- tf32 helpers ---------------------------------------------------
__device__ __forceinline__ uint32_t f2tf32(float f) {
    uint32_t r;
    asm("cvt.rna.tf32.f32 %0, %1;" : "=r"(r) : "f"(f));
    return r;
}
__device__ __forceinline__ void mma_tf32(float* c, const uint32_t* a,
                                         uint32_t b0, uint32_t b1) {
    asm volatile(
        "mma.sync.aligned.m16n8k8.row.col.f32.tf32.tf32.f32 "
        "{%0,%1,%2,%3}, {%4,%5,%6,%7}, {%8,%9}, {%0,%1,%2,%3};"
        : "+f"(c[0]), "+f"(c[1]), "+f"(c[2]), "+f"(c[3])
        : "r"(a[0]), "r"(a[1]), "r"(a[2]), "r"(a[3]), "r"(b0), "r"(b1));
}

// ---------------- TF32 GEMM: 128x128 tile, paired-fragment smem, LDS.64 ----------
// Layout: AsF[k8*4+tig][m][2] pair={k, k+4}; BsF[k8*4+tig][n][2]. Row stride 264
// u32 (264 mod 32 = 8 -> banks 8*tig + 2*grp, conflict-free). Double-buffered.
#define FRAG_STRIDE 264
#define AF_U32 (16 * FRAG_STRIDE)      // 4224
#define STAGE_U32 (2 * AF_U32)         // 8448 (A + B)
#define GEMM_SMEM_BYTES (2 * STAGE_U32 * 4)

template <int ASEL, int OUTSEL, int EPI>
__global__ void __launch_bounds__(256, 2)
k_gemm_tf32(const float* __restrict__ Aext, const float* __restrict__ W,
            float* outExt, int Nrows, int K, int M) {
    const float* A = selbuf_c<ASEL>(Aext);
    float* OUT = selbuf<OUTSEL>(outExt);
    extern __shared__ uint32_t dynsmem[];

    const int tid  = threadIdx.x;
    const int warp = tid >> 5;
    const int lane = tid & 31;
    const int warpRow = warp & 3;
    const int warpCol = warp >> 2;
    const int rowBase = blockIdx.x * 128;
    const int colBase = blockIdx.y * 128;
    const int tig = lane & 3;
    const int grp = lane >> 2;

    float acc[2][8][4];
#pragma unroll
    for (int mf = 0; mf < 2; mf++)
#pragma unroll
        for (int nf = 0; nf < 8; nf++)
#pragma unroll
            for (int q = 0; q < 4; q++) acc[mf][nf][q] = 0.0f;

    float4 ra[4], rb[4];
    // load slab 0
#pragma unroll
    for (int t = 0; t < 4; t++) {
        int idx = tid + t * 256;
        int m = idx >> 3, c4 = idx & 7;
        int gr = rowBase + m;
        ra[t] = (gr < Nrows) ? *(const float4*)(A + (size_t)gr * K + c4 * 4)
                             : make_float4(0.f, 0.f, 0.f, 0.f);
        int k = idx >> 5, b4 = idx & 31;
        rb[t] = *(const float4*)(W + (size_t)k * M + colBase + b4 * 4);
    }
    // store slab 0 -> stage 0 (paired layout)
    {
        uint32_t* AsF = dynsmem;
        uint32_t* BsF = dynsmem + AF_U32;
#pragma unroll
        for (int t = 0; t < 4; t++) {
            int idx = tid + t * 256;
            int m = idx >> 3, c4 = idx & 7;
            int ar = (c4 >> 1) * 4, ap = c4 & 1;
            AsF[(ar + 0) * FRAG_STRIDE + m * 2 + ap] = f2tf32(ra[t].x);
            AsF[(ar + 1) * FRAG_STRIDE + m * 2 + ap] = f2tf32(ra[t].y);
            AsF[(ar + 2) * FRAG_STRIDE + m * 2 + ap] = f2tf32(ra[t].z);
            AsF[(ar + 3) * FRAG_STRIDE + m * 2 + ap] = f2tf32(ra[t].w);
            int k = idx >> 5, b4 = idx & 31;
            int br = (k >> 3) * 4 + (k & 3), bp = (k >> 2) & 1;
            uint32_t* bq = BsF + br * FRAG_STRIDE + (b4 * 4) * 2 + bp;
            bq[0] = f2tf32(rb[t].x);
            bq[2] = f2tf32(rb[t].y);
            bq[4] = f2tf32(rb[t].z);
            bq[6] = f2tf32(rb[t].w);
        }
    }
    __syncthreads();

    const int niter = K >> 5;
    for (int i = 0; i < niter; i++) {
        if (i + 1 < niter) {
            int kb = (i + 1) << 5;
#pragma unroll
            for (int t = 0; t < 4; t++) {
                int idx = tid + t * 256;
                int m = idx >> 3, c4 = idx & 7;
                int gr = rowBase + m;
                ra[t] = (gr < Nrows)
                        ? *(const float4*)(A + (size_t)gr * K + kb + c4 * 4)
                        : make_float4(0.f, 0.f, 0.f, 0.f);
                int k = idx >> 5, b4 = idx & 31;
                rb[t] = *(const float4*)(W + (size_t)(kb + k) * M + colBase + b4 * 4);
            }
        }
        {
            const uint32_t* AsF = dynsmem + (i & 1) * STAGE_U32;
            const uint32_t* BsF = AsF + AF_U32;
#pragma unroll
            for (int k8 = 0; k8 < 4; k8++) {
                int base = (k8 * 4 + tig) * FRAG_STRIDE;
                uint32_t a[2][4];
#pragma unroll
                for (int mf = 0; mf < 2; mf++) {
                    int mrow = warpRow * 32 + mf * 16 + grp;
                    uint2 lo = *(const uint2*)&AsF[base + mrow * 2];
                    uint2 hi = *(const uint2*)&AsF[base + (mrow + 8) * 2];
                    a[mf][0] = lo.x; a[mf][1] = hi.x;
                    a[mf][2] = lo.y; a[mf][3] = hi.y;
                }
#pragma unroll
                for (int nf = 0; nf < 8; nf++) {
                    int ncol = warpCol * 64 + nf * 8 + grp;
                    uint2 bb = *(const uint2*)&BsF[base + ncol * 2];
                    mma_tf32(acc[0][nf], a[0], bb.x, bb.y);
                    mma_tf32(acc[1][nf], a[1], bb.x, bb.y);
                }
            }
        }
        if (i + 1 < niter) {
            uint32_t* AsF = dynsmem + ((i + 1) & 1) * STAGE_U32;
            uint32_t* BsF = AsF + AF_U32;
#pragma unroll
            for (int t = 0; t < 4; t++) {
                int idx = tid + t * 256;
                int m = idx >> 3, c4 = idx & 7;
                int ar = (c4 >> 1) * 4, ap = c4 & 1;
                AsF[(ar + 0) * FRAG_STRIDE + m * 2 + ap] = f2tf32(ra[t].x);
                AsF[(ar + 1) * FRAG_STRIDE + m * 2 + ap] = f2tf32(ra[t].y);
                AsF[(ar + 2) * FRAG_STRIDE + m * 2 + ap] = f2tf32(ra[t].z);
                AsF[(ar + 3) * FRAG_STRIDE + m * 2 + ap] = f2tf32(ra[t].w);
                int k = idx >> 5, b4 = idx & 31;
                int br = (k >> 3) * 4 + (k & 3), bp = (k >> 2) & 1;
                uint32_t* bq = BsF + br * FRAG_STRIDE + (b4 * 4) * 2 + bp;
                bq[0] = f2tf32(rb[t].x);
                bq[2] = f2tf32(rb[t].y);
                bq[4] = f2tf32(rb[t].z);
                bq[6] = f2tf32(rb[t].w);
            }
            __syncthreads();
        }
    }

#pragma unroll
    for (int mf = 0; mf < 2; mf++) {
        int row0 = rowBase + warpRow * 32 + mf * 16 + grp;
#pragma unroll
        for (int nf = 0; nf < 8; nf++) {
            int col = colBase + warpCol * 64 + nf * 8 + tig * 2;
            float2 v0 = make_float2(acc[mf][nf][0], acc[mf][nf][1]);
            float2 v1 = make_float2(acc[mf][nf][2], acc[mf][nf][3]);
            if constexpr (EPI == 1) {
                float2 s2 = *(const float2*)(g_s1 + col);
                float2 o2 = *(const float2*)(g_o1 + col);
                v0.x = fmaxf(fmaf(v0.x, s2.x, o2.x), 0.0f);
                v0.y = fmaxf(fmaf(v0.y, s2.y, o2.y), 0.0f);
                v1.x = fmaxf(fmaf(v1.x, s2.x, o2.x), 0.0f);
                v1.y = fmaxf(fmaf(v1.y, s2.y, o2.y), 0.0f);
            }
            if (row0 < Nrows)     *(float2*)(OUT + (size_t)row0 * M + col) = v0;
            if (row0 + 8 < Nrows) *(float2*)(OUT + (size_t)(row0 + 8) * M + col) = v1;
        }
    }
}

// ---------------- TF32 GEMM, N=40 (layer 3): 128x40 tile, reg-prefetch -----------
template <int ASEL>
__global__ void __launch_bounds__(256, 2)
k_gemm_tf32_n40(const float* __restrict__ Aext, const float* __restrict__ W,
                int Nrows) {
    const float* A = selbuf_c<ASEL>(Aext);
    constexpr int K = 256, M = 40;
    __shared__ uint32_t As[128][36];
    __shared__ uint32_t Bs[32][44];

    const int tid  = threadIdx.x;
    const int warp = tid >> 5;
    const int lane = tid & 31;
    const int rowBase = blockIdx.x * 128;
    const int tig = lane & 3;
    const int grp = lane >> 2;

    float acc[5][4];
#pragma unroll
    for (int nf = 0; nf < 5; nf++)
#pragma unroll
        for (int q = 0; q < 4; q++) acc[nf][q] = 0.0f;

    float4 ra[4];
    float4 rb[2];
#pragma unroll
    for (int t = 0; t < 4; t++) {
        int idx = tid + t * 256;
        int m = idx >> 3, c4 = idx & 7;
        int gr = rowBase + m;
        ra[t] = (gr < Nrows) ? *(const float4*)(A + (size_t)gr * K + c4 * 4)
                             : make_float4(0.f, 0.f, 0.f, 0.f);
    }
#pragma unroll
    for (int t = 0; t < 2; t++) {
        int idx = tid + t * 256;
        if (idx < 320) {
            int k = idx / 10, b4 = idx % 10;
            rb[t] = *(const float4*)(W + (size_t)k * M + b4 * 4);
        }
    }

    for (int k0 = 0; k0 < K; k0 += 32) {
#pragma unroll
        for (int t = 0; t < 4; t++) {
            int idx = tid + t * 256;
            int m = idx >> 3, c4 = idx & 7;
            As[m][c4 * 4 + 0] = f2tf32(ra[t].x);
            As[m][c4 * 4 + 1] = f2tf32(ra[t].y);
            As[m][c4 * 4 + 2] = f2tf32(ra[t].z);
            As[m][c4 * 4 + 3] = f2tf32(ra[t].w);
        }
#pragma unroll
        for (int t = 0; t < 2; t++) {
            int idx = tid + t * 256;
            if (idx < 320) {
                int k = idx / 10, b4 = idx % 10;
                Bs[k][b4 * 4 + 0] = f2tf32(rb[t].x);
                Bs[k][b4 * 4 + 1] = f2tf32(rb[t].y);
                Bs[k][b4 * 4 + 2] = f2tf32(rb[t].z);
                Bs[k][b4 * 4 + 3] = f2tf32(rb[t].w);
            }
        }
        __syncthreads();
        if (k0 + 32 < K) {
#pragma unroll
            for (int t = 0; t < 4; t++) {
                int idx = tid + t * 256;
                int m = idx >> 3, c4 = idx & 7;
                int gr = rowBase + m;
                ra[t] = (gr < Nrows)
                        ? *(const float4*)(A + (size_t)gr * K + (k0 + 32) + c4 * 4)
                        : make_float4(0.f, 0.f, 0.f, 0.f);
            }
#pragma unroll
            for (int t = 0; t < 2; t++) {
                int idx = tid + t * 256;
                if (idx < 320) {
                    int k = idx / 10, b4 = idx % 10;
                    rb[t] = *(const float4*)(W + (size_t)(k0 + 32 + k) * M + b4 * 4);
                }
            }
        }
#pragma unroll
        for (int k8 = 0; k8 < 4; k8++) {
            int mrow = warp * 16 + grp;
            uint32_t a[4];
            a[0] = As[mrow][k8 * 8 + tig];
            a[1] = As[mrow + 8][k8 * 8 + tig];
            a[2] = As[mrow][k8 * 8 + tig + 4];
            a[3] = As[mrow + 8][k8 * 8 + tig + 4];
#pragma unroll
            for (int nf = 0; nf < 5; nf++) {
                int ncol = nf * 8 + grp;
                uint32_t b0 = Bs[k8 * 8 + tig][ncol];
                uint32_t b1 = Bs[k8 * 8 + tig + 4][ncol];
                mma_tf32(acc[nf], a, b0, b1);
            }
        }
        __syncthreads();
    }

    int row0 = rowBase + warp * 16 + grp;
#pragma unroll
    for (int nf = 0; nf < 5; nf++) {
        int col = nf * 8 + tig * 2;
        if (row0 < Nrows)
            *(float2*)(g_b0 + (size_t)row0 * M + col) =
                make_float2(acc[nf][0], acc[nf][1]);
        if (row0 + 8 < Nrows)
            *(float2*)(g_b0 + (size_t)(row0 + 8) * M + col) =
                make_float2(acc[nf][2], acc[nf][3]);
    }
}

// ---------------- launch (kernel launches ONLY + func attrs) ---------------------
extern "C" void kernel_launch(void* const* d_in, const int* in_sizes, int n_in,
                              void* d_out, int out_size) {
    const float* x  = (const float*)d_in[0];
    const int*   ei = (const int*)d_in[1];   // int32 (JAX x64 disabled)
    const float* W1 = (const float*)d_in[2];
    const float* b1 = (const float*)d_in[3];
    const float* g1 = (const float*)d_in[4];
    const float* be1 = (const float*)d_in[5];
    const float* m1 = (const float*)d_in[6];
    const float* v1 = (const float*)d_in[7];
    const float* W2 = (const float*)d_in[8];
    const float* b2 = (const float*)d_in[9];
    const float* g2 = (const float*)d_in[10];
    const float* be2 = (const float*)d_in[11];
    const float* m2 = (const float*)d_in[12];
    const float* v2 = (const float*)d_in[13];
    const float* W3 = (const float*)d_in[14];
    const float* b3 = (const float*)d_in[15];
    float* out = (float*)d_out;

    int E = in_sizes[1] / 2;

    bool emb_in_out = ((long long)out_size >= (long long)NN * (D_OUT + D_H));
    float* emb = out + (size_t)NN * D_OUT;

    cudaFuncSetAttribute(k_gemm_tf32<2, 1, 1>,
                         cudaFuncAttributeMaxDynamicSharedMemorySize, GEMM_SMEM_BYTES);
    cudaFuncSetAttribute(k_gemm_tf32<1, 0, 0>,
                         cudaFuncAttributeMaxDynamicSharedMemorySize, GEMM_SMEM_BYTES);

    const int T = 256;
    int nblk = (NN + T - 1) / T;
    int eblk = (E + T - 1) / T;
    dim3 gemm_h((NN + 127) / 128, D_H / 128);
    int gemm_o_grid = (NN + 127) / 128;
    int agg32_grid = (NN + 7) / 8;     // TPR=32, 8 rows/block
    int aggsm_grid = (NN + 15) / 16;   // fused agg+softmax, 16 rows/block

    // ---- CSR build + BN params ----
    k_zero_counts<<<nblk, T>>>();
    k_count<<<eblk, T>>>(ei, E);
    k_scan1<<<NB_SCAN, 256>>>();
    k_scan2<<<1, 1024>>>();
    k_scan3<<<NB_SCAN, 256>>>(E);
    k_norms<<<nblk, T>>>();
    k_fill<<<eblk, T>>>(ei, E);
    k_bnparams<<<1, 256>>>(b1, g1, be1, m1, v1, b2, g2, be2, m2, v2);

    // ---- layer 1: g_b2 = agg(x) [128 cols]; g_b1 = relu(bn1(g_b2@W1)) [tf32] ----
    k_csr_agg<32, 32, 32, 3, 2, 0><<<agg32_grid, T>>>(x, nullptr, 0);
    k_gemm_tf32<2, 1, 1><<<gemm_h, T, GEMM_SMEM_BYTES>>>(nullptr, W1, nullptr,
                                                         NN, D_IN, D_H);

    // ---- layer 2: g_b0 = g_b1@W2 [tf32]; emb = relu(bn2(agg(g_b0))), 2 passes ---
    k_gemm_tf32<1, 0, 0><<<gemm_h, T, GEMM_SMEM_BYTES>>>(nullptr, W2, nullptr,
                                                         NN, D_H, D_H);
    if (emb_in_out) {
        k_csr_agg<32, 32, 64, 0, 3, 1><<<agg32_grid, T>>>(nullptr, emb, 0);
        k_csr_agg<32, 32, 64, 0, 3, 1><<<agg32_grid, T>>>(nullptr, emb, 32);
    } else {
        k_csr_agg<32, 32, 64, 0, 2, 1><<<agg32_grid, T>>>(nullptr, nullptr, 0);
        k_csr_agg<32, 32, 64, 0, 2, 1><<<agg32_grid, T>>>(nullptr, nullptr, 32);
    }

    // ---- layer 3: g_b0 = emb@W3 (40 cols, tf32); fused agg+softmax -> out ----
    if (emb_in_out) {
        k_gemm_tf32_n40<3><<<gemm_o_grid, T>>>(emb, W3, NN);
        k_agg_softmax<0><<<aggsm_grid, T>>>(nullptr, b3, out);
    } else {
        k_gemm_tf32_n40<2><<<gemm_o_grid, T>>>(nullptr, W3, NN);
        k_agg_softmax<0><<<aggsm_grid, T>>>(nullptr, b3, out);
    }
}

// round 14
// speedup vs baseline: 1.1935x; 1.1935x over previous
#include <cuda_runtime.h>
#include <cuda_bf16.h>
#include <math.h>
#include <stdint.h>

#define NN 169343
#define EE_MAX 2400000
#define D_IN 128
#define D_H  256
#define D_OUT 40
#define EPS 1e-5f
#define NB_SCAN ((NN + 255) / 256)   // 662

// ---------------- scratch (allocation-free __device__ globals) -------------------
__device__ float g_dinv[NN];
__device__ float g_selfnorm[NN];
__device__ int   g_counts[NN];
__device__ int   g_cursor[NN];
__device__ int   g_rowptr[NN + 1];
__device__ int   g_partial[NB_SCAN];
__device__ int2  g_csr[EE_MAX];            // {src, w-as-bits} interleaved
__device__ float g_s1[D_H], g_o1[D_H];     // fused BN1 params
__device__ float g_s2[D_H], g_o2[D_H];     // fused BN2 params
__device__ float g_b0[(size_t)NN * D_H];   // H (gemm output)
__device__ float g_b1[(size_t)NN * D_H];   // act1
__device__ float g_b2[(size_t)NN * D_H];   // agg(x) / emb fallback

template <int SEL>
__device__ __forceinline__ float* selbuf(float* ext) {
    if constexpr (SEL == 0) return g_b0;
    else if constexpr (SEL == 1) return g_b1;
    else if constexpr (SEL == 2) return g_b2;
    else return ext;
}
template <int SEL>
__device__ __forceinline__ const float* selbuf_c(const float* ext) {
    if constexpr (SEL == 0) return g_b0;
    else if constexpr (SEL == 1) return g_b1;
    else if constexpr (SEL == 2) return g_b2;
    else return ext;
}

// ---------------- CSR build ------------------------------------------------------
__global__ void k_zero_counts() {
    int i = blockIdx.x * blockDim.x + threadIdx.x;
    if (i < NN) g_counts[i] = 0;
}
__global__ void k_count(const int* __restrict__ ei, int E) {
    int e = blockIdx.x * blockDim.x + threadIdx.x;
    if (e < E) atomicAdd(&g_counts[ei[E + e]], 1);
}
__global__ void k_scan1() {
    __shared__ int s[256];
    int gid = blockIdx.x * 256 + threadIdx.x;
    int v = (gid < NN) ? g_counts[gid] : 0;
    s[threadIdx.x] = v;
    __syncthreads();
#pragma unroll
    for (int off = 1; off < 256; off <<= 1) {
        int t = (threadIdx.x >= off) ? s[threadIdx.x - off] : 0;
        __syncthreads();
        s[threadIdx.x] += t;
        __syncthreads();
    }
    if (gid < NN) g_rowptr[gid] = s[threadIdx.x] - v;   // exclusive
    if (threadIdx.x == 255) g_partial[blockIdx.x] = s[255];
}
__global__ void k_scan2() {
    __shared__ int s[1024];
    int v = (threadIdx.x < NB_SCAN) ? g_partial[threadIdx.x] : 0;
    s[threadIdx.x] = v;
    __syncthreads();
#pragma unroll
    for (int off = 1; off < 1024; off <<= 1) {
        int t = (threadIdx.x >= off) ? s[threadIdx.x - off] : 0;
        __syncthreads();
        s[threadIdx.x] += t;
        __syncthreads();
    }
    if (threadIdx.x < NB_SCAN) g_partial[threadIdx.x] = s[threadIdx.x] - v;
}
__global__ void k_scan3(int E) {
    int gid = blockIdx.x * 256 + threadIdx.x;
    if (gid < NN) g_rowptr[gid] += g_partial[blockIdx.x];
    if (gid == 0) g_rowptr[NN] = E;
}
__global__ void k_norms() {
    int i = blockIdx.x * blockDim.x + threadIdx.x;
    if (i < NN) {
        int r0 = g_rowptr[i];
        float d = (float)(g_rowptr[i + 1] - r0 + 1);
        g_dinv[i]     = rsqrtf(d);
        g_selfnorm[i] = 1.0f / d;
        g_cursor[i]   = r0;
    }
}
__global__ void k_fill(const int* __restrict__ ei, int E) {
    int e = blockIdx.x * blockDim.x + threadIdx.x;
    if (e < E) {
        int src = ei[e];
        int dst = ei[E + e];
        int pos = atomicAdd(&g_cursor[dst], 1);
        float w = g_dinv[src] * g_dinv[dst];
        g_csr[pos] = make_int2(src, __float_as_int(w));
    }
}
__global__ void k_bnparams(const float* __restrict__ b1, const float* __restrict__ g1,
                           const float* __restrict__ be1, const float* __restrict__ m1,
                           const float* __restrict__ v1,
                           const float* __restrict__ b2, const float* __restrict__ g2,
                           const float* __restrict__ be2, const float* __restrict__ m2,
                           const float* __restrict__ v2) {
    int c = threadIdx.x;
    if (c < D_H) {
        float s = g1[c] * rsqrtf(v1[c] + EPS);
        g_s1[c] = s;
        g_o1[c] = be1[c] + (b1[c] - m1[c]) * s;
        s = g2[c] * rsqrtf(v2[c] + EPS);
        g_s2[c] = s;
        g_o2[c] = be2[c] + (b2[c] - m2[c]) * s;
    }
}

// ---------------- CSR aggregation ------------------------------------------------
template <int C4, int TPR, int ROWST4, int SRCSEL, int DSTSEL, int EPI>
__global__ void k_csr_agg(const float* __restrict__ srcExt, float* dstExt, int colOff4) {
    const float* __restrict__ SRC = selbuf_c<SRCSEL>(srcExt);
    float* DST = selbuf<DSTSEL>(dstExt);
    constexpr int RPB = 256 / TPR;
    int row = blockIdx.x * RPB + threadIdx.x / TPR;
    int c   = threadIdx.x % TPR;
    if (row >= NN || c >= C4) return;
    int col4 = colOff4 + c;

    float sn = g_selfnorm[row];
    float4 h = *((const float4*)(SRC + (size_t)row * (ROWST4 * 4)) + col4);
    float4 acc = make_float4(h.x * sn, h.y * sn, h.z * sn, h.w * sn);

    int e0 = g_rowptr[row], e1 = g_rowptr[row + 1];
#pragma unroll 2
    for (int e = e0; e < e1; e++) {
        int2 p = g_csr[e];
        float w = __int_as_float(p.y);
        float4 v = *((const float4*)(SRC + (size_t)p.x * (ROWST4 * 4)) + col4);
        acc.x = fmaf(v.x, w, acc.x);
        acc.y = fmaf(v.y, w, acc.y);
        acc.z = fmaf(v.z, w, acc.z);
        acc.w = fmaf(v.w, w, acc.w);
    }
    if constexpr (EPI == 1) {
        float4 s4 = *((const float4*)g_s2 + col4);
        float4 o4 = *((const float4*)g_o2 + col4);
        acc.x = fmaxf(fmaf(acc.x, s4.x, o4.x), 0.0f);
        acc.y = fmaxf(fmaf(acc.y, s4.y, o4.y), 0.0f);
        acc.z = fmaxf(fmaf(acc.z, s4.z, o4.z), 0.0f);
        acc.w = fmaxf(fmaf(acc.w, s4.w, o4.w), 0.0f);
    }
    *((float4*)(DST + (size_t)row * (ROWST4 * 4)) + col4) = acc;
}

// ---------------- fused layer-3 agg + bias + log-softmax -------------------------
// SRC rows of 40 floats (logits pre-agg in g_b0). 16 lanes per row, lanes 0..9
// active (10 float4 per row). Width-16 shuffles for max/sum.
template <int SRCSEL>
__global__ void k_agg_softmax(const float* __restrict__ srcExt,
                              const float* __restrict__ b3, float* __restrict__ OUT) {
    const float* __restrict__ SRC = selbuf_c<SRCSEL>(srcExt);
    int tid = threadIdx.x;
    int row = blockIdx.x * 16 + tid / 16;
    int c   = tid % 16;
    int rowc = (row < NN) ? row : NN - 1;
    bool active = (c < 10);

    float4 acc = make_float4(0.f, 0.f, 0.f, 0.f);
    if (active) {
        float sn = g_selfnorm[rowc];
        float4 h = *((const float4*)(SRC + (size_t)rowc * D_OUT) + c);
        acc = make_float4(h.x * sn, h.y * sn, h.z * sn, h.w * sn);
        int e0 = g_rowptr[rowc], e1 = g_rowptr[rowc + 1];
#pragma unroll 2
        for (int e = e0; e < e1; e++) {
            int2 p = g_csr[e];
            float w = __int_as_float(p.y);
            float4 v = *((const float4*)(SRC + (size_t)p.x * D_OUT) + c);
            acc.x = fmaf(v.x, w, acc.x);
            acc.y = fmaf(v.y, w, acc.y);
            acc.z = fmaf(v.z, w, acc.z);
            acc.w = fmaf(v.w, w, acc.w);
        }
        float4 bb = *((const float4*)b3 + c);
        acc.x += bb.x; acc.y += bb.y; acc.z += bb.z; acc.w += bb.w;
    }
    float m = active ? fmaxf(fmaxf(acc.x, acc.y), fmaxf(acc.z, acc.w)) : -1e30f;
#pragma unroll
    for (int o = 8; o > 0; o >>= 1)
        m = fmaxf(m, __shfl_xor_sync(0xffffffffu, m, o, 16));
    float s = active ? (__expf(acc.x - m) + __expf(acc.y - m) +
                        __expf(acc.z - m) + __expf(acc.w - m)) : 0.0f;
#pragma unroll
    for (int o = 8; o > 0; o >>= 1)
        s += __shfl_xor_sync(0xffffffffu, s, o, 16);
    float ls = __logf(s);
    if (active && row < NN) {
        float4 o4 = make_float4(acc.x - m - ls, acc.y - m - ls,
                                acc.z - m - ls, acc.w - m - ls);
        *((float4*)(OUT + (size_t)row * D_OUT) + c) = o4;
    }
}

// ---------------- tf32 helpers ---------------------------------------------------
__device__ __forceinline__ uint32_t f2tf32(float f) {
    uint32_t r;
    asm("cvt.rna.tf32.f32 %0, %1;" : "=r"(r) : "f"(f));
    return r;
}
__device__ __forceinline__ void mma_tf32(float* c, const uint32_t* a,
                                         uint32_t b0, uint32_t b1) {
    asm volatile(
        "mma.sync.aligned.m16n8k8.row.col.f32.tf32.tf32.f32 "
        "{%0,%1,%2,%3}, {%4,%5,%6,%7}, {%8,%9}, {%0,%1,%2,%3};"
        : "+f"(c[0]), "+f"(c[1]), "+f"(c[2]), "+f"(c[3])
        : "r"(a[0]), "r"(a[1]), "r"(a[2]), "r"(a[3]), "r"(b0), "r"(b1));
}

// ---------------- TF32 GEMM: 128x128 tile, double-buffered dynamic smem ----------
// (R12-proven layout.) 8 warps (4x2), warp 32x64. A row-major [Nrows,K],
// W row-major [K,M] (M=256). Stage = As[128][36] + Bs[32][136] u32.
#define AS_U32 (128 * 36)
#define BS_U32 (32 * 136)
#define STAGE_U32 (AS_U32 + BS_U32)
#define GEMM_SMEM_BYTES (2 * STAGE_U32 * 4)

template <int ASEL, int OUTSEL, int EPI>
__global__ void __launch_bounds__(256, 2)
k_gemm_tf32(const float* __restrict__ Aext, const float* __restrict__ W,
            float* outExt, int Nrows, int K, int M) {
    const float* A = selbuf_c<ASEL>(Aext);
    float* OUT = selbuf<OUTSEL>(outExt);
    extern __shared__ uint32_t dynsmem[];

    const int tid  = threadIdx.x;
    const int warp = tid >> 5;
    const int lane = tid & 31;
    const int warpRow = warp & 3;
    const int warpCol = warp >> 2;
    const int rowBase = blockIdx.x * 128;
    const int colBase = blockIdx.y * 128;
    const int tig = lane & 3;
    const int grp = lane >> 2;

    float acc[2][8][4];
#pragma unroll
    for (int mf = 0; mf < 2; mf++)
#pragma unroll
        for (int nf = 0; nf < 8; nf++)
#pragma unroll
            for (int q = 0; q < 4; q++) acc[mf][nf][q] = 0.0f;

    float4 ra[4], rb[4];
    // load slab 0
#pragma unroll
    for (int t = 0; t < 4; t++) {
        int idx = tid + t * 256;
        int m = idx >> 3, c4 = idx & 7;
        int gr = rowBase + m;
        ra[t] = (gr < Nrows) ? *(const float4*)(A + (size_t)gr * K + c4 * 4)
                             : make_float4(0.f, 0.f, 0.f, 0.f);
        int k = idx >> 5, b4 = idx & 31;
        rb[t] = *(const float4*)(W + (size_t)k * M + colBase + b4 * 4);
    }
    // store slab 0 -> stage 0
    {
        uint32_t* As = dynsmem;
        uint32_t* Bs = dynsmem + AS_U32;
#pragma unroll
        for (int t = 0; t < 4; t++) {
            int idx = tid + t * 256;
            int m = idx >> 3, c4 = idx & 7;
            As[m * 36 + c4 * 4 + 0] = f2tf32(ra[t].x);
            As[m * 36 + c4 * 4 + 1] = f2tf32(ra[t].y);
            As[m * 36 + c4 * 4 + 2] = f2tf32(ra[t].z);
            As[m * 36 + c4 * 4 + 3] = f2tf32(ra[t].w);
            int k = idx >> 5, b4 = idx & 31;
            Bs[k * 136 + b4 * 4 + 0] = f2tf32(rb[t].x);
            Bs[k * 136 + b4 * 4 + 1] = f2tf32(rb[t].y);
            Bs[k * 136 + b4 * 4 + 2] = f2tf32(rb[t].z);
            Bs[k * 136 + b4 * 4 + 3] = f2tf32(rb[t].w);
        }
    }
    __syncthreads();

    const int niter = K >> 5;
    for (int i = 0; i < niter; i++) {
        // prefetch slab i+1 to regs (overlaps MMA below)
        if (i + 1 < niter) {
            int kb = (i + 1) << 5;
#pragma unroll
            for (int t = 0; t < 4; t++) {
                int idx = tid + t * 256;
                int m = idx >> 3, c4 = idx & 7;
                int gr = rowBase + m;
                ra[t] = (gr < Nrows)
                        ? *(const float4*)(A + (size_t)gr * K + kb + c4 * 4)
                        : make_float4(0.f, 0.f, 0.f, 0.f);
                int k = idx >> 5, b4 = idx & 31;
                rb[t] = *(const float4*)(W + (size_t)(kb + k) * M + colBase + b4 * 4);
            }
        }
        // MMA on stage i&1
        {
            const uint32_t* As = dynsmem + (i & 1) * STAGE_U32;
            const uint32_t* Bs = As + AS_U32;
#pragma unroll
            for (int k8 = 0; k8 < 4; k8++) {
                uint32_t a[2][4];
#pragma unroll
                for (int mf = 0; mf < 2; mf++) {
                    int mrow = warpRow * 32 + mf * 16 + grp;
                    a[mf][0] = As[mrow * 36 + k8 * 8 + tig];
                    a[mf][1] = As[(mrow + 8) * 36 + k8 * 8 + tig];
                    a[mf][2] = As[mrow * 36 + k8 * 8 + tig + 4];
                    a[mf][3] = As[(mrow + 8) * 36 + k8 * 8 + tig + 4];
                }
#pragma unroll
                for (int nf = 0; nf < 8; nf++) {
                    int ncol = warpCol * 64 + nf * 8 + grp;
                    uint32_t b0 = Bs[(k8 * 8 + tig) * 136 + ncol];
                    uint32_t b1 = Bs[(k8 * 8 + tig + 4) * 136 + ncol];
                    mma_tf32(acc[0][nf], a[0], b0, b1);
                    mma_tf32(acc[1][nf], a[1], b0, b1);
                }
            }
        }
        // store slab i+1 -> stage (i+1)&1
        if (i + 1 < niter) {
            uint32_t* As = dynsmem + ((i + 1) & 1) * STAGE_U32;
            uint32_t* Bs = As + AS_U32;
#pragma unroll
            for (int t = 0; t < 4; t++) {
                int idx = tid + t * 256;
                int m = idx >> 3, c4 = idx & 7;
                As[m * 36 + c4 * 4 + 0] = f2tf32(ra[t].x);
                As[m * 36 + c4 * 4 + 1] = f2tf32(ra[t].y);
                As[m * 36 + c4 * 4 + 2] = f2tf32(ra[t].z);
                As[m * 36 + c4 * 4 + 3] = f2tf32(ra[t].w);
                int k = idx >> 5, b4 = idx & 31;
                Bs[k * 136 + b4 * 4 + 0] = f2tf32(rb[t].x);
                Bs[k * 136 + b4 * 4 + 1] = f2tf32(rb[t].y);
                Bs[k * 136 + b4 * 4 + 2] = f2tf32(rb[t].z);
                Bs[k * 136 + b4 * 4 + 3] = f2tf32(rb[t].w);
            }
            __syncthreads();
        }
    }

#pragma unroll
    for (int mf = 0; mf < 2; mf++) {
        int row0 = rowBase + warpRow * 32 + mf * 16 + grp;
#pragma unroll
        for (int nf = 0; nf < 8; nf++) {
            int col = colBase + warpCol * 64 + nf * 8 + tig * 2;
            float2 v0 = make_float2(acc[mf][nf][0], acc[mf][nf][1]);
            float2 v1 = make_float2(acc[mf][nf][2], acc[mf][nf][3]);
            if constexpr (EPI == 1) {
                float2 s2 = *(const float2*)(g_s1 + col);
                float2 o2 = *(const float2*)(g_o1 + col);
                v0.x = fmaxf(fmaf(v0.x, s2.x, o2.x), 0.0f);
                v0.y = fmaxf(fmaf(v0.y, s2.y, o2.y), 0.0f);
                v1.x = fmaxf(fmaf(v1.x, s2.x, o2.x), 0.0f);
                v1.y = fmaxf(fmaf(v1.y, s2.y, o2.y), 0.0f);
            }
            if (row0 < Nrows)     *(float2*)(OUT + (size_t)row0 * M + col) = v0;
            if (row0 + 8 < Nrows) *(float2*)(OUT + (size_t)(row0 + 8) * M + col) = v1;
        }
    }
}

// ---------------- TF32 GEMM, N=40 (layer 3): 128x40 tile, reg-prefetch -----------
template <int ASEL>
__global__ void __launch_bounds__(256, 2)
k_gemm_tf32_n40(const float* __restrict__ Aext, const float* __restrict__ W,
                int Nrows) {
    const float* A = selbuf_c<ASEL>(Aext);
    constexpr int K = 256, M = 40;
    __shared__ uint32_t As[128][36];
    __shared__ uint32_t Bs[32][44];

    const int tid  = threadIdx.x;
    const int warp = tid >> 5;
    const int lane = tid & 31;
    const int rowBase = blockIdx.x * 128;
    const int tig = lane & 3;
    const int grp = lane >> 2;

    float acc[5][4];
#pragma unroll
    for (int nf = 0; nf < 5; nf++)
#pragma unroll
        for (int q = 0; q < 4; q++) acc[nf][q] = 0.0f;

    float4 ra[4];
    float4 rb[2];
#pragma unroll
    for (int t = 0; t < 4; t++) {
        int idx = tid + t * 256;
        int m = idx >> 3, c4 = idx & 7;
        int gr = rowBase + m;
        ra[t] = (gr < Nrows) ? *(const float4*)(A + (size_t)gr * K + c4 * 4)
                             : make_float4(0.f, 0.f, 0.f, 0.f);
    }
#pragma unroll
    for (int t = 0; t < 2; t++) {
        int idx = tid + t * 256;
        if (idx < 320) {
            int k = idx / 10, b4 = idx % 10;
            rb[t] = *(const float4*)(W + (size_t)k * M + b4 * 4);
        }
    }

    for (int k0 = 0; k0 < K; k0 += 32) {
#pragma unroll
        for (int t = 0; t < 4; t++) {
            int idx = tid + t * 256;
            int m = idx >> 3, c4 = idx & 7;
            As[m][c4 * 4 + 0] = f2tf32(ra[t].x);
            As[m][c4 * 4 + 1] = f2tf32(ra[t].y);
            As[m][c4 * 4 + 2] = f2tf32(ra[t].z);
            As[m][c4 * 4 + 3] = f2tf32(ra[t].w);
        }
#pragma unroll
        for (int t = 0; t < 2; t++) {
            int idx = tid + t * 256;
            if (idx < 320) {
                int k = idx / 10, b4 = idx % 10;
                Bs[k][b4 * 4 + 0] = f2tf32(rb[t].x);
                Bs[k][b4 * 4 + 1] = f2tf32(rb[t].y);
                Bs[k][b4 * 4 + 2] = f2tf32(rb[t].z);
                Bs[k][b4 * 4 + 3] = f2tf32(rb[t].w);
            }
        }
        __syncthreads();
        if (k0 + 32 < K) {
#pragma unroll
            for (int t = 0; t < 4; t++) {
                int idx = tid + t * 256;
                int m = idx >> 3, c4 = idx & 7;
                int gr = rowBase + m;
                ra[t] = (gr < Nrows)
                        ? *(const float4*)(A + (size_t)gr * K + (k0 + 32) + c4 * 4)
                        : make_float4(0.f, 0.f, 0.f, 0.f);
            }
#pragma unroll
            for (int t = 0; t < 2; t++) {
                int idx = tid + t * 256;
                if (idx < 320) {
                    int k = idx / 10, b4 = idx % 10;
                    rb[t] = *(const float4*)(W + (size_t)(k0 + 32 + k) * M + b4 * 4);
                }
            }
        }
#pragma unroll
        for (int k8 = 0; k8 < 4; k8++) {
            int mrow = warp * 16 + grp;
            uint32_t a[4];
            a[0] = As[mrow][k8 * 8 + tig];
            a[1] = As[mrow + 8][k8 * 8 + tig];
            a[2] = As[mrow][k8 * 8 + tig + 4];
            a[3] = As[mrow + 8][k8 * 8 + tig + 4];
#pragma unroll
            for (int nf = 0; nf < 5; nf++) {
                int ncol = nf * 8 + grp;
                uint32_t b0 = Bs[k8 * 8 + tig][ncol];
                uint32_t b1 = Bs[k8 * 8 + tig + 4][ncol];
                mma_tf32(acc[nf], a, b0, b1);
            }
        }
        __syncthreads();
    }

    int row0 = rowBase + warp * 16 + grp;
#pragma unroll
    for (int nf = 0; nf < 5; nf++) {
        int col = nf * 8 + tig * 2;
        if (row0 < Nrows)
            *(float2*)(g_b0 + (size_t)row0 * M + col) =
                make_float2(acc[nf][0], acc[nf][1]);
        if (row0 + 8 < Nrows)
            *(float2*)(g_b0 + (size_t)(row0 + 8) * M + col) =
                make_float2(acc[nf][2], acc[nf][3]);
    }
}

// ---------------- launch (kernel launches ONLY + func attrs) ---------------------
extern "C" void kernel_launch(void* const* d_in, const int* in_sizes, int n_in,
                              void* d_out, int out_size) {
    const float* x  = (const float*)d_in[0];
    const int*   ei = (const int*)d_in[1];   // int32 (JAX x64 disabled)
    const float* W1 = (const float*)d_in[2];
    const float* b1 = (const float*)d_in[3];
    const float* g1 = (const float*)d_in[4];
    const float* be1 = (const float*)d_in[5];
    const float* m1 = (const float*)d_in[6];
    const float* v1 = (const float*)d_in[7];
    const float* W2 = (const float*)d_in[8];
    const float* b2 = (const float*)d_in[9];
    const float* g2 = (const float*)d_in[10];
    const float* be2 = (const float*)d_in[11];
    const float* m2 = (const float*)d_in[12];
    const float* v2 = (const float*)d_in[13];
    const float* W3 = (const float*)d_in[14];
    const float* b3 = (const float*)d_in[15];
    float* out = (float*)d_out;

    int E = in_sizes[1] / 2;

    bool emb_in_out = ((long long)out_size >= (long long)NN * (D_OUT + D_H));
    float* emb = out + (size_t)NN * D_OUT;

    cudaFuncSetAttribute(k_gemm_tf32<2, 1, 1>,
                         cudaFuncAttributeMaxDynamicSharedMemorySize, GEMM_SMEM_BYTES);
    cudaFuncSetAttribute(k_gemm_tf32<1, 0, 0>,
                         cudaFuncAttributeMaxDynamicSharedMemorySize, GEMM_SMEM_BYTES);

    const int T = 256;
    int nblk = (NN + T - 1) / T;
    int eblk = (E + T - 1) / T;
    dim3 gemm_h((NN + 127) / 128, D_H / 128);
    int gemm_o_grid = (NN + 127) / 128;
    int agg32_grid = (NN + 7) / 8;     // TPR=32, 8 rows/block
    int aggsm_grid = (NN + 15) / 16;   // fused agg+softmax, 16 rows/block

    // ---- CSR build + BN params ----
    k_zero_counts<<<nblk, T>>>();
    k_count<<<eblk, T>>>(ei, E);
    k_scan1<<<NB_SCAN, 256>>>();
    k_scan2<<<1, 1024>>>();
    k_scan3<<<NB_SCAN, 256>>>(E);
    k_norms<<<nblk, T>>>();
    k_fill<<<eblk, T>>>(ei, E);
    k_bnparams<<<1, 256>>>(b1, g1, be1, m1, v1, b2, g2, be2, m2, v2);

    // ---- layer 1: g_b2 = agg(x) [128 cols]; g_b1 = relu(bn1(g_b2@W1)) [tf32] ----
    k_csr_agg<32, 32, 32, 3, 2, 0><<<agg32_grid, T>>>(x, nullptr, 0);
    k_gemm_tf32<2, 1, 1><<<gemm_h, T, GEMM_SMEM_BYTES>>>(nullptr, W1, nullptr,
                                                         NN, D_IN, D_H);

    // ---- layer 2: g_b0 = g_b1@W2 [tf32]; emb = relu(bn2(agg(g_b0))), 2 passes ---
    k_gemm_tf32<1, 0, 0><<<gemm_h, T, GEMM_SMEM_BYTES>>>(nullptr, W2, nullptr,
                                                         NN, D_H, D_H);
    if (emb_in_out) {
        k_csr_agg<32, 32, 64, 0, 3, 1><<<agg32_grid, T>>>(nullptr, emb, 0);
        k_csr_agg<32, 32, 64, 0, 3, 1><<<agg32_grid, T>>>(nullptr, emb, 32);
    } else {
        k_csr_agg<32, 32, 64, 0, 2, 1><<<agg32_grid, T>>>(nullptr, nullptr, 0);
        k_csr_agg<32, 32, 64, 0, 2, 1><<<agg32_grid, T>>>(nullptr, nullptr, 32);
    }

    // ---- layer 3: g_b0 = emb@W3 (40 cols, tf32); fused agg+softmax -> out ----
    if (emb_in_out)
        k_gemm_tf32_n40<3><<<gemm_o_grid, T>>>(emb, W3, NN);
    else
        k_gemm_tf32_n40<2><<<gemm_o_grid, T>>>(nullptr, W3, NN);
    k_agg_softmax<0><<<aggsm_grid, T>>>(nullptr, b3, out);
}